// round 16
// baseline (speedup 1.0000x reference)
#include <cuda_runtime.h>
#include <cuda_fp16.h>
#include <cstdint>

#define NN 50000
#define NE 600000
#define NSEG (NN*4)
#define NSTEP 5
typedef unsigned short u16; typedef uint32_t u32;

// ---------------- device scratch ----------------
__device__ u16   g_sh[(long)NN*512], g_sl[(long)NN*512];   // s hi/lo planes [N][512]
__device__ u16   g_ahi[(long)NN*128], g_alo[(long)NN*128]; // a hi/lo planes
__device__ u16   g_hhi[(long)NN*128], g_hlo[(long)NN*128]; // h hi/lo planes
__device__ float g_h[(long)NN*128];                        // h fp32
__device__ float g_g[(long)NN*512];                        // gate pre-activations
__device__ float g_cnt[NSEG];
__device__ int   g_deg[NSEG], g_roff[NSEG+1], g_cur[NSEG];
__device__ int   g_bsum[256];
__device__ int   g_srcs[NE];
__device__ u16   g_wch[8*8192];                            // Wcat chunks (pre-swizzled fp16)
__device__ u16   g_wgh[16*8192];                           // gate W chunks

// ---------------- helpers ----------------
__device__ __forceinline__ u32 smem_u32(const void* p){
    u32 a; asm("{ .reg .u64 t; cvta.to.shared.u64 t, %1; cvt.u32.u64 %0, t; }":"=r"(a):"l"(p)); return a;
}
__device__ __forceinline__ u32 swz(u32 o){ return o ^ ((o>>3)&0x70); }
__device__ __forceinline__ void hl(float x, u16& h_, u16& l_){
    __half hh = __float2half_rn(x);
    __half ll = __float2half_rn(x - __half2float(hh));
    h_ = __half_as_ushort(hh); l_ = __half_as_ushort(ll);
}
__device__ __forceinline__ void ldsm4(u32* r, u32 a){
    asm volatile("ldmatrix.sync.aligned.m8n8.x4.shared.b16 {%0,%1,%2,%3}, [%4];"
                 : "=r"(r[0]),"=r"(r[1]),"=r"(r[2]),"=r"(r[3]) : "r"(a));
}
__device__ __forceinline__ void mma16816(float* c, const u32* a, const u32* b){
    asm volatile("mma.sync.aligned.m16n8k16.row.col.f32.f16.f16.f32 "
                 "{%0,%1,%2,%3}, {%4,%5,%6,%7}, {%8,%9}, {%0,%1,%2,%3};"
                 : "+f"(c[0]),"+f"(c[1]),"+f"(c[2]),"+f"(c[3])
                 : "r"(a[0]),"r"(a[1]),"r"(a[2]),"r"(a[3]),"r"(b[0]),"r"(b[1]));
}
__device__ __forceinline__ void cpa(u32 dst, const void* src, int sz){
    asm volatile("cp.async.cg.shared.global [%0], [%1], 16, %2;" :: "r"(dst),"l"(src),"r"(sz) : "memory");
}
#define CP_COMMIT() asm volatile("cp.async.commit_group;" ::: "memory")
#define CP_WAIT1()  asm volatile("cp.async.wait_group 1;" ::: "memory")
#define CP_WAIT0()  asm volatile("cp.async.wait_group 0;" ::: "memory")

// stage layout: Ah@0, Al@16K, Bh@32K ; stride 48K; 2 stages
#define STAGE 49152
#define SMB   (2*STAGE)

__device__ __forceinline__ void load_a_tile(u32 stage, const u16* __restrict__ SH,
    const u16* __restrict__ SL, int row0, long rstride, int coloff, int t)
{
#pragma unroll
    for (int i=0;i<4;i++){
        int g = t + i*256;
        int r = g>>3, c8 = (g&7)*8;
        int row = row0 + r;
        int ok = (row < NN);
        long ga = (long)(ok?row:0)*rstride + coloff + c8;
        u32 off = swz((u32)(r*128 + c8*2));
        cpa(stage + off,          SH + ga, ok?16:0);
        cpa(stage + 16384 + off,  SL + ga, ok?16:0);
    }
}
__device__ __forceinline__ void load_b_tile(u32 stage, const u16* __restrict__ BH, int chunk, int t)
{
    const uint4* bh = (const uint4*)(BH + (long)chunk*8192);
#pragma unroll
    for (int i=0;i<4;i++){
        int g = t + i*256;
        cpa(stage + 32768 + g*16, bh+g, 16);
    }
}
__device__ __forceinline__ void compute_chunk(u32 sb, float c[4][4][4], int wm, int wn, int lane){
    int arow = wm + (lane&15);
    int akof = (lane>>4)*8;
    int brow = wn + (lane&7) + ((lane&16)>>1);
    int bkof = ((lane>>3)&1)*8;
#pragma unroll
    for (int kb=0;kb<4;kb++){
        u32 ah[4][4], al[4][4], bh[2][4];
#pragma unroll
        for (int mi=0;mi<4;mi++){
            u32 off = swz((u32)((arow + mi*16)*128 + (kb*16 + akof)*2));
            ldsm4(ah[mi], sb + off);
            ldsm4(al[mi], sb + 16384 + off);
        }
#pragma unroll
        for (int nj=0;nj<2;nj++){
            u32 off = swz((u32)((brow + nj*16)*128 + (kb*16 + bkof)*2));
            ldsm4(bh[nj], sb + 32768 + off);
        }
#pragma unroll
        for (int mi=0;mi<4;mi++)
#pragma unroll
            for (int ni=0;ni<4;ni++){
                int nj = ni>>1, s = (ni&1)*2;
                mma16816(c[mi][ni], ah[mi], bh[nj]+s);
                mma16816(c[mi][ni], al[mi], bh[nj]+s);
            }
    }
}

// ---------------- merged setup: weights + h init ----------------
#define SETUP_TOT (196608 + NN*64)
__global__ void __launch_bounds__(256) k_setupinit(const float* __restrict__ W_lin,
    const float* __restrict__ w_ih, const float* __restrict__ w_hh,
    const float* __restrict__ hin)
{
    for (int idx = blockIdx.x*256+threadIdx.x; idx < SETUP_TOT; idx += gridDim.x*256){
        if (idx < 65536){                        // Wcat: B[f][kg], kg = type*128+d
            int f = idx>>9, kg = idx&511;
            float val = W_lin[(kg>>7)*16384 + f*128 + (kg&127)];
            u32 dst = (u32)(kg>>6)*8192 + (swz((u32)(f*128 + (kg&63)*2))>>1);
            g_wch[dst] = __half_as_ushort(__float2half_rn(val));
        } else if (idx < 196608){                // gate W: nb in {r,z,i_n,h_n}
            int j = idx-65536, nb = j>>15, r = j&32767, f = r>>8, kg = r&255;
            float v = 0.f;
            if (nb==0) v = (kg<128) ? w_ih[f*128+kg]        : w_hh[f*128+kg-128];
            else if (nb==1) v = (kg<128) ? w_ih[(128+f)*128+kg] : w_hh[(128+f)*128+kg-128];
            else if (nb==2) v = (kg<128) ? w_ih[(256+f)*128+kg] : 0.f;
            else            v = (kg<128) ? 0.f : w_hh[(256+f)*128+kg-128];
            u32 dst = (u32)(nb*4 + (kg>>6))*8192 + (swz((u32)(f*128 + (kg&63)*2))>>1);
            g_wgh[dst] = __half_as_ushort(__float2half_rn(v));
        } else {                                 // h init (2 elems per item)
            int tid = idx - 196608;
            float2 v = *(const float2*)&hin[tid*2];
            *(float2*)&g_h[tid*2] = v;
            u16 h0,l0,h1,l1; hl(v.x,h0,l0); hl(v.y,h1,l1);
            *(u32*)&g_hhi[tid*2] = (u32)h0 | ((u32)h1<<16);
            *(u32*)&g_hlo[tid*2] = (u32)l0 | ((u32)l1<<16);
        }
    }
}

// ---------------- CSR build over (dst,type) segments ----------------
__global__ void __launch_bounds__(256) k_hist(const int* __restrict__ dst,
    const int* __restrict__ ety){
    int e = blockIdx.x*256+threadIdx.x;
    if (e < NE) atomicAdd(&g_deg[dst[e]*4 + (ety[e]-1)], 1);
}
__global__ void __launch_bounds__(1024) k_scan1(){
    __shared__ int wsum[32];
    int t = threadIdx.x, lane = t&31, w = t>>5;
    int i = blockIdx.x*1024 + t;
    int v = (i<NSEG) ? g_deg[i] : 0;
    int s = v;
    #pragma unroll
    for (int o=1;o<32;o<<=1){ int u=__shfl_up_sync(~0u,s,o); if(lane>=o) s+=u; }
    if (lane==31) wsum[w]=s;
    __syncthreads();
    if (w==0){ int ws=wsum[lane];
        #pragma unroll
        for (int o=1;o<32;o<<=1){ int u=__shfl_up_sync(~0u,ws,o); if(lane>=o) ws+=u; }
        wsum[lane]=ws; }
    __syncthreads();
    int excl = s - v + (w>0 ? wsum[w-1] : 0);
    if (i<NSEG){ g_roff[i] = excl; g_deg[i] = 0; }   // self-restoring for graph replay
    if (t==1023) g_bsum[blockIdx.x] = excl + v;
}
__global__ void __launch_bounds__(1024) k_scan23(){
    __shared__ int wsum[32]; __shared__ int btot;
    int b = blockIdx.x, t = threadIdx.x, lane = t&31, w = t>>5;
    int v = (t < b) ? g_bsum[t] : 0;
    #pragma unroll
    for (int o=16;o>0;o>>=1) v += __shfl_down_sync(~0u,v,o);
    if (lane==0) wsum[w]=v;
    __syncthreads();
    if (w==0){
        int s = wsum[lane];
        #pragma unroll
        for (int o=16;o>0;o>>=1) s += __shfl_down_sync(~0u,s,o);
        if (lane==0) btot = s;
    }
    __syncthreads();
    int i = b*1024 + t;
    if (i<NSEG){ int r = g_roff[i]+btot; g_roff[i]=r; g_cur[i]=r; }
    if (b==0 && t==0) g_roff[NSEG]=NE;
}
__global__ void __launch_bounds__(256) k_place(const int* __restrict__ src,
    const int* __restrict__ dst, const int* __restrict__ ety){
    int e = blockIdx.x*256+threadIdx.x;
    if (e >= NE) return;
    int pos = atomicAdd(&g_cur[dst[e]*4 + (ety[e]-1)], 1);
    g_srcs[pos] = src[e];
}

// ---------------- s-build: two segments per warp (half-warp each) ----------------
__global__ void __launch_bounds__(256) k_sbuild(){
    int wrp  = (blockIdx.x*256+threadIdx.x)>>5;
    int lane = threadIdx.x&31;
    int half = lane>>4, hl16 = lane&15;
    int seg  = wrp*2 + half;
    if (seg >= NSEG) return;
    int beg = g_roff[seg], end = g_roff[seg+1];
    float4 a0 = {0,0,0,0}, a1 = {0,0,0,0};
    int e = beg;
    for (; e+1 < end; e += 2){
        const float* h0 = &g_h[(long)g_srcs[e]*128   + hl16*8];
        const float* h1 = &g_h[(long)g_srcs[e+1]*128 + hl16*8];
        float4 v00 = *(const float4*)h0,     v01 = *(const float4*)(h0+4);
        float4 v10 = *(const float4*)h1,     v11 = *(const float4*)(h1+4);
        a0.x += v00.x + v10.x; a0.y += v00.y + v10.y;
        a0.z += v00.z + v10.z; a0.w += v00.w + v10.w;
        a1.x += v01.x + v11.x; a1.y += v01.y + v11.y;
        a1.z += v01.z + v11.z; a1.w += v01.w + v11.w;
    }
    if (e < end){
        const float* h0 = &g_h[(long)g_srcs[e]*128 + hl16*8];
        float4 v0 = *(const float4*)h0, v1 = *(const float4*)(h0+4);
        a0.x += v0.x; a0.y += v0.y; a0.z += v0.z; a0.w += v0.w;
        a1.x += v1.x; a1.y += v1.y; a1.z += v1.z; a1.w += v1.w;
    }
    int node = seg>>2, k = seg&3;
    long base = (long)node*512 + k*128 + hl16*8;
    u16 h4[8], l4[8];
    const float* f0 = (const float*)&a0; const float* f1 = (const float*)&a1;
    #pragma unroll
    for (int i=0;i<4;i++){ hl(f0[i], h4[i], l4[i]); hl(f1[i], h4[4+i], l4[4+i]); }
    *(uint2*)&g_sh[base]   = *(uint2*)&h4[0];
    *(uint2*)&g_sh[base+4] = *(uint2*)&h4[4];
    *(uint2*)&g_sl[base]   = *(uint2*)&l4[0];
    *(uint2*)&g_sl[base+4] = *(uint2*)&l4[4];
    if (hl16==0) g_cnt[seg] = (float)(end-beg);
}

// ---------------- GEMM A: a = s @ Wc^T (+cnt.b_lin) -> fp16 planes ----------------
__global__ void __launch_bounds__(256,2) k_gemm_a(const float* __restrict__ b_lin){
    extern __shared__ __align__(1024) char sm[];
    u32 sb = smem_u32(sm);
    int t = threadIdx.x, lane = t&31, wid = t>>5;
    int row0 = blockIdx.x*128;
    int wm = (wid&1)*64, wn = (wid>>1)*32;
    float cacc[4][4][4];
#pragma unroll
    for (int a=0;a<4;a++)
#pragma unroll
        for (int b=0;b<4;b++)
#pragma unroll
            for (int d=0;d<4;d++) cacc[a][b][d]=0.f;

    load_a_tile(sb, g_sh, g_sl, row0, 512, 0, t);
    load_b_tile(sb, g_wch, 0, t);
    CP_COMMIT();
    for (int c=0;c<8;c++){
        u32 st = sb + (u32)(c&1)*STAGE;
        if (c<7){
            u32 nx = sb + (u32)((c+1)&1)*STAGE;
            load_a_tile(nx, g_sh, g_sl, row0, 512, (c+1)*64, t);
            load_b_tile(nx, g_wch, c+1, t);
            CP_COMMIT();
            CP_WAIT1();
        } else CP_WAIT0();
        __syncthreads();
        compute_chunk(st, cacc, wm, wn, lane);
        __syncthreads();
    }
    // epilogue: + cnt.b_lin, write fp16 hi/lo planes
    float* bls = (float*)sm;
    bls[t] = b_lin[t]; bls[t+256] = b_lin[256+t];
    __syncthreads();
    int tg = (lane&3)*2, gr = lane>>2;
#pragma unroll
    for (int mi=0;mi<4;mi++)
#pragma unroll
        for (int ni=0;ni<4;ni++){
            int col = wn + ni*8 + tg;
#pragma unroll
            for (int hf=0;hf<2;hf++){
                int r2 = row0 + wm + mi*16 + gr + hf*8;
                if (r2 < NN){
                    const float4 cn = *(const float4*)&g_cnt[r2*4];
                    float v0 = cacc[mi][ni][hf*2+0] + cn.x*bls[col]   + cn.y*bls[128+col]
                             + cn.z*bls[256+col]   + cn.w*bls[384+col];
                    float v1 = cacc[mi][ni][hf*2+1] + cn.x*bls[col+1] + cn.y*bls[129+col]
                             + cn.z*bls[257+col]   + cn.w*bls[385+col];
                    u16 h0,l0,h1,l1; hl(v0,h0,l0); hl(v1,h1,l1);
                    *(u32*)&g_ahi[(long)r2*128+col] = (u32)h0 | ((u32)h1<<16);
                    *(u32*)&g_alo[(long)r2*128+col] = (u32)l0 | ((u32)l1<<16);
                }
            }
        }
}

// ---------------- GEMM G (R5-proven 4-column grid) ----------------
__global__ void __launch_bounds__(256,2) k_gemm_g(){
    extern __shared__ __align__(1024) char sm[];
    u32 sb = smem_u32(sm);
    int t = threadIdx.x, lane = t&31, wid = t>>5;
    int row0 = blockIdx.x*128;
    int nb = blockIdx.y;
    int c0 = (nb==3)?2:0, c1 = (nb==2)?2:4;
    int wm = (wid&1)*64, wn = (wid>>1)*32;
    float cacc[4][4][4];
#pragma unroll
    for (int a=0;a<4;a++)
#pragma unroll
        for (int b=0;b<4;b++)
#pragma unroll
            for (int d=0;d<4;d++) cacc[a][b][d]=0.f;

    {
        const u16* SH = (c0<2)? g_ahi : g_hhi;
        const u16* SL = (c0<2)? g_alo : g_hlo;
        load_a_tile(sb, SH, SL, row0, 128, (c0&1)*64, t);
        load_b_tile(sb, g_wgh, nb*4+c0, t);
        CP_COMMIT();
    }
    for (int c=c0;c<c1;c++){
        u32 st = sb + (u32)((c-c0)&1)*STAGE;
        if (c+1<c1){
            u32 nx = sb + (u32)((c+1-c0)&1)*STAGE;
            const u16* SH = (c+1<2)? g_ahi : g_hhi;
            const u16* SL = (c+1<2)? g_alo : g_hlo;
            load_a_tile(nx, SH, SL, row0, 128, ((c+1)&1)*64, t);
            load_b_tile(nx, g_wgh, nb*4+c+1, t);
            CP_COMMIT();
            CP_WAIT1();
        } else CP_WAIT0();
        __syncthreads();
        compute_chunk(st, cacc, wm, wn, lane);
        __syncthreads();
    }
    int tg = (lane&3)*2, gr = lane>>2;
#pragma unroll
    for (int mi=0;mi<4;mi++)
#pragma unroll
        for (int ni=0;ni<4;ni++){
            int col = wn + ni*8 + tg;
#pragma unroll
            for (int hf=0;hf<2;hf++){
                int r2 = row0 + wm + mi*16 + gr + hf*8;
                if (r2 < NN)
                    *(float2*)&g_g[(long)r2*512 + nb*128 + col] =
                        make_float2(cacc[mi][ni][hf*2+0], cacc[mi][ni][hf*2+1]);
            }
        }
}

// ---------------- GRU gates (float4; plane writes skipped on last step) ----------------
__global__ void __launch_bounds__(256) k_gru(const float* __restrict__ b_ih,
    const float* __restrict__ b_hh, float* __restrict__ hout, int last)
{
    int tid = blockIdx.x*256+threadIdx.x;
    if (tid >= NN*32) return;
    int row = tid>>5, p = (tid&31)*4;
    long gb = (long)row*512;
    float4 rv = *(const float4*)&g_g[gb + p];
    float4 zv = *(const float4*)&g_g[gb + 128 + p];
    float4 iv = *(const float4*)&g_g[gb + 256 + p];
    float4 nv = *(const float4*)&g_g[gb + 384 + p];
    float4 hv = *(const float4*)&g_h[(long)row*128 + p];
    const float* rp=(const float*)&rv; const float* zp=(const float*)&zv;
    const float* ip=(const float*)&iv; const float* np=(const float*)&nv;
    const float* hp=(const float*)&hv;
    float o[4]; u16 hh4[4], ll4[4];
#pragma unroll
    for (int j=0;j<4;j++){
        int f = p + j;
        float r_ = 1.f/(1.f + __expf(-(rp[j] + b_ih[f] + b_hh[f])));
        float z_ = 1.f/(1.f + __expf(-(zp[j] + b_ih[128+f] + b_hh[128+f])));
        float n_ = tanhf(ip[j] + b_ih[256+f] + r_*(np[j] + b_hh[256+f]));
        float out = (1.f - z_)*n_ + z_*hp[j];
        o[j] = out; hl(out, hh4[j], ll4[j]);
    }
    *(float4*)&hout[(long)row*128 + p] = *(float4*)o;
    if (!last){
        *(uint2*)&g_hhi[(long)row*128 + p] = *(uint2*)hh4;
        *(uint2*)&g_hlo[(long)row*128 + p] = *(uint2*)ll4;
    }
}

// ---------------- launch ----------------
extern "C" void kernel_launch(void* const* d_in, const int* in_sizes, int n_in,
                              void* d_out, int out_size)
{
    const float* h_in  = (const float*)d_in[0];
    const int*   src   = (const int*)d_in[1];
    const int*   dst   = (const int*)d_in[2];
    const int*   ety   = (const int*)d_in[3];
    const float* W_lin = (const float*)d_in[4];
    const float* b_lin = (const float*)d_in[5];
    const float* w_ih  = (const float*)d_in[6];
    const float* w_hh  = (const float*)d_in[7];
    const float* b_ih  = (const float*)d_in[8];
    const float* b_hh  = (const float*)d_in[9];

    cudaFuncSetAttribute(k_gemm_a, cudaFuncAttributeMaxDynamicSharedMemorySize, SMB);
    cudaFuncSetAttribute(k_gemm_g, cudaFuncAttributeMaxDynamicSharedMemorySize, SMB);

    float* h_p; cudaGetSymbolAddress((void**)&h_p, g_h);

    const int scan_blocks = (NSEG + 1023) / 1024;   // 196

    k_hist<<<(NE+255)/256,256>>>(dst, ety);
    k_scan1<<<scan_blocks,1024>>>();
    k_scan23<<<scan_blocks,1024>>>();
    k_place<<<(NE+255)/256,256>>>(src, dst, ety);
    k_setupinit<<<768,256>>>(W_lin, w_ih, w_hh, h_in);

    const int tilesA = (NN+127)/128;   // 391
    for (int step=0; step<NSTEP; step++){
        k_sbuild<<<(NSEG/2*32+255)/256,256>>>();
        k_gemm_a<<<tilesA,256,SMB>>>(b_lin);
        k_gemm_g<<<dim3(tilesA,4),256,SMB>>>();
        float* hout = (step==NSTEP-1) ? (float*)d_out : h_p;
        k_gru<<<(NN*32+255)/256,256>>>(b_ih, b_hh, hout, step==NSTEP-1);
    }
    (void)in_sizes; (void)n_in; (void)out_size;
}

// round 17
// speedup vs baseline: 1.0358x; 1.0358x over previous
#include <cuda_runtime.h>
#include <cuda_fp16.h>
#include <cstdint>

#define NN 50000
#define NE 600000
#define NSEG (NN*4)
#define NSTEP 5
typedef unsigned short u16; typedef uint32_t u32;

// ---------------- device scratch ----------------
__device__ u16   g_sh[(long)NN*512], g_sl[(long)NN*512];   // s hi/lo planes [N][512]
__device__ u16   g_ahi[(long)NN*128], g_alo[(long)NN*128]; // a hi/lo planes
__device__ u16   g_hhi[(long)NN*128], g_hlo[(long)NN*128]; // h hi/lo planes
__device__ float g_h[(long)NN*128];                        // h fp32
__device__ float g_g[(long)NN*512];                        // gate pre-activations
__device__ float g_cnt[NSEG];
__device__ int   g_deg[NSEG], g_roff[NSEG+1], g_cur[NSEG];
__device__ int   g_bsum[256];
__device__ int   g_srcs[NE];
__device__ u16   g_wch[8*8192];                            // Wcat chunks (pre-swizzled fp16)
__device__ u16   g_wgh[16*8192];                           // gate W chunks

// ---------------- helpers ----------------
__device__ __forceinline__ u32 smem_u32(const void* p){
    u32 a; asm("{ .reg .u64 t; cvta.to.shared.u64 t, %1; cvt.u32.u64 %0, t; }":"=r"(a):"l"(p)); return a;
}
__device__ __forceinline__ u32 swz(u32 o){ return o ^ ((o>>3)&0x70); }
__device__ __forceinline__ void hl(float x, u16& h_, u16& l_){
    __half hh = __float2half_rn(x);
    __half ll = __float2half_rn(x - __half2float(hh));
    h_ = __half_as_ushort(hh); l_ = __half_as_ushort(ll);
}
__device__ __forceinline__ void ldsm4(u32* r, u32 a){
    asm volatile("ldmatrix.sync.aligned.m8n8.x4.shared.b16 {%0,%1,%2,%3}, [%4];"
                 : "=r"(r[0]),"=r"(r[1]),"=r"(r[2]),"=r"(r[3]) : "r"(a));
}
__device__ __forceinline__ void mma16816(float* c, const u32* a, const u32* b){
    asm volatile("mma.sync.aligned.m16n8k16.row.col.f32.f16.f16.f32 "
                 "{%0,%1,%2,%3}, {%4,%5,%6,%7}, {%8,%9}, {%0,%1,%2,%3};"
                 : "+f"(c[0]),"+f"(c[1]),"+f"(c[2]),"+f"(c[3])
                 : "r"(a[0]),"r"(a[1]),"r"(a[2]),"r"(a[3]),"r"(b[0]),"r"(b[1]));
}
__device__ __forceinline__ void cpa(u32 dst, const void* src, int sz){
    asm volatile("cp.async.cg.shared.global [%0], [%1], 16, %2;" :: "r"(dst),"l"(src),"r"(sz) : "memory");
}
#define CP_COMMIT() asm volatile("cp.async.commit_group;" ::: "memory")
#define CP_WAIT1()  asm volatile("cp.async.wait_group 1;" ::: "memory")
#define CP_WAIT0()  asm volatile("cp.async.wait_group 0;" ::: "memory")

// stage layout: Ah@0, Al@16K, Bh@32K ; stride 48K; 2 stages
#define STAGE 49152
#define SMB   (2*STAGE)

__device__ __forceinline__ void load_a_tile(u32 stage, const u16* __restrict__ SH,
    const u16* __restrict__ SL, int row0, long rstride, int coloff, int t)
{
#pragma unroll
    for (int i=0;i<4;i++){
        int g = t + i*256;
        int r = g>>3, c8 = (g&7)*8;
        int row = row0 + r;
        int ok = (row < NN);
        long ga = (long)(ok?row:0)*rstride + coloff + c8;
        u32 off = swz((u32)(r*128 + c8*2));
        cpa(stage + off,          SH + ga, ok?16:0);
        cpa(stage + 16384 + off,  SL + ga, ok?16:0);
    }
}
__device__ __forceinline__ void load_b_tile(u32 stage, const u16* __restrict__ BH, int chunk, int t)
{
    const uint4* bh = (const uint4*)(BH + (long)chunk*8192);
#pragma unroll
    for (int i=0;i<4;i++){
        int g = t + i*256;
        cpa(stage + 32768 + g*16, bh+g, 16);
    }
}
__device__ __forceinline__ void compute_chunk(u32 sb, float c[4][4][4], int wm, int wn, int lane){
    int arow = wm + (lane&15);
    int akof = (lane>>4)*8;
    int brow = wn + (lane&7) + ((lane&16)>>1);
    int bkof = ((lane>>3)&1)*8;
#pragma unroll
    for (int kb=0;kb<4;kb++){
        u32 ah[4][4], al[4][4], bh[2][4];
#pragma unroll
        for (int mi=0;mi<4;mi++){
            u32 off = swz((u32)((arow + mi*16)*128 + (kb*16 + akof)*2));
            ldsm4(ah[mi], sb + off);
            ldsm4(al[mi], sb + 16384 + off);
        }
#pragma unroll
        for (int nj=0;nj<2;nj++){
            u32 off = swz((u32)((brow + nj*16)*128 + (kb*16 + bkof)*2));
            ldsm4(bh[nj], sb + 32768 + off);
        }
#pragma unroll
        for (int mi=0;mi<4;mi++)
#pragma unroll
            for (int ni=0;ni<4;ni++){
                int nj = ni>>1, s = (ni&1)*2;
                mma16816(c[mi][ni], ah[mi], bh[nj]+s);
                mma16816(c[mi][ni], al[mi], bh[nj]+s);
            }
    }
}
// write one 128x128 result block to g_g[:, blk*128 ..]
__device__ __forceinline__ void store_g(float c[4][4][4], int row0, int wm, int wn,
                                        int lane, int blk){
    int tg = (lane&3)*2, gr = lane>>2;
#pragma unroll
    for (int mi=0;mi<4;mi++)
#pragma unroll
        for (int ni=0;ni<4;ni++){
            int col = wn + ni*8 + tg;
#pragma unroll
            for (int hf=0;hf<2;hf++){
                int r2 = row0 + wm + mi*16 + gr + hf*8;
                if (r2 < NN)
                    *(float2*)&g_g[(long)r2*512 + blk*128 + col] =
                        make_float2(c[mi][ni][hf*2+0], c[mi][ni][hf*2+1]);
            }
        }
}

// ---------------- merged setup: weights + h init ----------------
#define SETUP_TOT (196608 + NN*64)
__global__ void __launch_bounds__(256) k_setupinit(const float* __restrict__ W_lin,
    const float* __restrict__ w_ih, const float* __restrict__ w_hh,
    const float* __restrict__ hin)
{
    for (int idx = blockIdx.x*256+threadIdx.x; idx < SETUP_TOT; idx += gridDim.x*256){
        if (idx < 65536){                        // Wcat: B[f][kg], kg = type*128+d
            int f = idx>>9, kg = idx&511;
            float val = W_lin[(kg>>7)*16384 + f*128 + (kg&127)];
            u32 dst = (u32)(kg>>6)*8192 + (swz((u32)(f*128 + (kg&63)*2))>>1);
            g_wch[dst] = __half_as_ushort(__float2half_rn(val));
        } else if (idx < 196608){                // gate W: nb in {r,z,i_n,h_n}
            int j = idx-65536, nb = j>>15, r = j&32767, f = r>>8, kg = r&255;
            float v = 0.f;
            if (nb==0) v = (kg<128) ? w_ih[f*128+kg]        : w_hh[f*128+kg-128];
            else if (nb==1) v = (kg<128) ? w_ih[(128+f)*128+kg] : w_hh[(128+f)*128+kg-128];
            else if (nb==2) v = (kg<128) ? w_ih[(256+f)*128+kg] : 0.f;
            else            v = (kg<128) ? 0.f : w_hh[(256+f)*128+kg-128];
            u32 dst = (u32)(nb*4 + (kg>>6))*8192 + (swz((u32)(f*128 + (kg&63)*2))>>1);
            g_wgh[dst] = __half_as_ushort(__float2half_rn(v));
        } else {                                 // h init (2 elems per item)
            int tid = idx - 196608;
            float2 v = *(const float2*)&hin[tid*2];
            *(float2*)&g_h[tid*2] = v;
            u16 h0,l0,h1,l1; hl(v.x,h0,l0); hl(v.y,h1,l1);
            *(u32*)&g_hhi[tid*2] = (u32)h0 | ((u32)h1<<16);
            *(u32*)&g_hlo[tid*2] = (u32)l0 | ((u32)l1<<16);
        }
    }
}

// ---------------- CSR build over (dst,type) segments ----------------
__global__ void __launch_bounds__(256) k_hist(const int* __restrict__ dst,
    const int* __restrict__ ety){
    int e = blockIdx.x*256+threadIdx.x;
    if (e < NE) atomicAdd(&g_deg[dst[e]*4 + (ety[e]-1)], 1);
}
__global__ void __launch_bounds__(1024) k_scan1(){
    __shared__ int wsum[32];
    int t = threadIdx.x, lane = t&31, w = t>>5;
    int i = blockIdx.x*1024 + t;
    int v = (i<NSEG) ? g_deg[i] : 0;
    int s = v;
    #pragma unroll
    for (int o=1;o<32;o<<=1){ int u=__shfl_up_sync(~0u,s,o); if(lane>=o) s+=u; }
    if (lane==31) wsum[w]=s;
    __syncthreads();
    if (w==0){ int ws=wsum[lane];
        #pragma unroll
        for (int o=1;o<32;o<<=1){ int u=__shfl_up_sync(~0u,ws,o); if(lane>=o) ws+=u; }
        wsum[lane]=ws; }
    __syncthreads();
    int excl = s - v + (w>0 ? wsum[w-1] : 0);
    if (i<NSEG){ g_roff[i] = excl; g_deg[i] = 0; }   // self-restoring for graph replay
    if (t==1023) g_bsum[blockIdx.x] = excl + v;
}
__global__ void __launch_bounds__(1024) k_scan23(){
    __shared__ int wsum[32]; __shared__ int btot;
    int b = blockIdx.x, t = threadIdx.x, lane = t&31, w = t>>5;
    int v = (t < b) ? g_bsum[t] : 0;
    #pragma unroll
    for (int o=16;o>0;o>>=1) v += __shfl_down_sync(~0u,v,o);
    if (lane==0) wsum[w]=v;
    __syncthreads();
    if (w==0){
        int s = wsum[lane];
        #pragma unroll
        for (int o=16;o>0;o>>=1) s += __shfl_down_sync(~0u,s,o);
        if (lane==0) btot = s;
    }
    __syncthreads();
    int i = b*1024 + t;
    if (i<NSEG){ int r = g_roff[i]+btot; g_roff[i]=r; g_cur[i]=r; }
    if (b==0 && t==0) g_roff[NSEG]=NE;
}
__global__ void __launch_bounds__(256) k_place(const int* __restrict__ src,
    const int* __restrict__ dst, const int* __restrict__ ety){
    int e = blockIdx.x*256+threadIdx.x;
    if (e >= NE) return;
    int pos = atomicAdd(&g_cur[dst[e]*4 + (ety[e]-1)], 1);
    g_srcs[pos] = src[e];
}

// ---------------- s-build: warp per (node,type) segment (R5-exact) ----------------
__global__ void __launch_bounds__(256) k_sbuild(){
    int seg = (blockIdx.x*256+threadIdx.x)>>5, lane = threadIdx.x&31;
    if (seg >= NSEG) return;
    int beg = g_roff[seg], end = g_roff[seg+1];
    float4 a = {0,0,0,0};
    int e = beg;
    for (; e+1 < end; e += 2){
        int s0 = g_srcs[e], s1 = g_srcs[e+1];
        float4 v0 = *(const float4*)&g_h[(long)s0*128 + lane*4];
        float4 v1 = *(const float4*)&g_h[(long)s1*128 + lane*4];
        a.x += v0.x + v1.x; a.y += v0.y + v1.y;
        a.z += v0.z + v1.z; a.w += v0.w + v1.w;
    }
    if (e < end){
        float4 v = *(const float4*)&g_h[(long)g_srcs[e]*128 + lane*4];
        a.x += v.x; a.y += v.y; a.z += v.z; a.w += v.w;
    }
    int node = seg>>2, k = seg&3;
    long base = (long)node*512 + k*128 + lane*4;
    u16 h4[4], l4[4]; const float* f = (const float*)&a;
    #pragma unroll
    for (int i=0;i<4;i++) hl(f[i], h4[i], l4[i]);
    *(uint2*)&g_sh[base] = *(uint2*)h4;
    *(uint2*)&g_sl[base] = *(uint2*)l4;
    if (lane==0) g_cnt[seg] = (float)(end-beg);
}

// ---------------- GEMM A (y=0) + h_n gate block (y=1, tail fill) ----------------
// y=0: a = s @ Wc^T (+cnt.b_lin) -> fp16 a planes        (8 chunks, K=512)
// y=1: g_g[:,384:512] = h @ W_hn^T  (2 chunks, K=128) — depends only on h planes
__global__ void __launch_bounds__(256,2) k_gemm_a(const float* __restrict__ b_lin){
    extern __shared__ __align__(1024) char sm[];
    u32 sb = smem_u32(sm);
    int t = threadIdx.x, lane = t&31, wid = t>>5;
    int row0 = blockIdx.x*128;
    int wm = (wid&1)*64, wn = (wid>>1)*32;
    float cacc[4][4][4];
#pragma unroll
    for (int a=0;a<4;a++)
#pragma unroll
        for (int b=0;b<4;b++)
#pragma unroll
            for (int d=0;d<4;d++) cacc[a][b][d]=0.f;

    if (blockIdx.y == 1){
        // ---- h_n block ----
        load_a_tile(sb, g_hhi, g_hlo, row0, 128, 0, t);
        load_b_tile(sb, g_wgh, 14, t);
        CP_COMMIT();
        for (int c=0;c<2;c++){
            u32 st = sb + (u32)(c&1)*STAGE;
            if (c==0){
                u32 nx = sb + STAGE;
                load_a_tile(nx, g_hhi, g_hlo, row0, 128, 64, t);
                load_b_tile(nx, g_wgh, 15, t);
                CP_COMMIT();
                CP_WAIT1();
            } else CP_WAIT0();
            __syncthreads();
            compute_chunk(st, cacc, wm, wn, lane);
            __syncthreads();
        }
        store_g(cacc, row0, wm, wn, lane, 3);
        return;
    }

    // ---- a-GEMM ----
    load_a_tile(sb, g_sh, g_sl, row0, 512, 0, t);
    load_b_tile(sb, g_wch, 0, t);
    CP_COMMIT();
    for (int c=0;c<8;c++){
        u32 st = sb + (u32)(c&1)*STAGE;
        if (c<7){
            u32 nx = sb + (u32)((c+1)&1)*STAGE;
            load_a_tile(nx, g_sh, g_sl, row0, 512, (c+1)*64, t);
            load_b_tile(nx, g_wch, c+1, t);
            CP_COMMIT();
            CP_WAIT1();
        } else CP_WAIT0();
        __syncthreads();
        compute_chunk(st, cacc, wm, wn, lane);
        __syncthreads();
    }
    // epilogue: + cnt.b_lin, write fp16 hi/lo planes
    float* bls = (float*)sm;
    bls[t] = b_lin[t]; bls[t+256] = b_lin[256+t];
    __syncthreads();
    int tg = (lane&3)*2, gr = lane>>2;
#pragma unroll
    for (int mi=0;mi<4;mi++)
#pragma unroll
        for (int ni=0;ni<4;ni++){
            int col = wn + ni*8 + tg;
#pragma unroll
            for (int hf=0;hf<2;hf++){
                int r2 = row0 + wm + mi*16 + gr + hf*8;
                if (r2 < NN){
                    const float4 cn = *(const float4*)&g_cnt[r2*4];
                    float v0 = cacc[mi][ni][hf*2+0] + cn.x*bls[col]   + cn.y*bls[128+col]
                             + cn.z*bls[256+col]   + cn.w*bls[384+col];
                    float v1 = cacc[mi][ni][hf*2+1] + cn.x*bls[col+1] + cn.y*bls[129+col]
                             + cn.z*bls[257+col]   + cn.w*bls[385+col];
                    u16 h0,l0,h1,l1; hl(v0,h0,l0); hl(v1,h1,l1);
                    *(u32*)&g_ahi[(long)r2*128+col] = (u32)h0 | ((u32)h1<<16);
                    *(u32*)&g_alo[(long)r2*128+col] = (u32)l0 | ((u32)l1<<16);
                }
            }
        }
}

// ---------------- GEMM G: nb in {0,1,2} (r, z, i_n) ----------------
__global__ void __launch_bounds__(256,2) k_gemm_g(){
    extern __shared__ __align__(1024) char sm[];
    u32 sb = smem_u32(sm);
    int t = threadIdx.x, lane = t&31, wid = t>>5;
    int row0 = blockIdx.x*128;
    int nb = blockIdx.y;                       // 0,1,2
    int c1 = (nb==2)?2:4;
    int wm = (wid&1)*64, wn = (wid>>1)*32;
    float cacc[4][4][4];
#pragma unroll
    for (int a=0;a<4;a++)
#pragma unroll
        for (int b=0;b<4;b++)
#pragma unroll
            for (int d=0;d<4;d++) cacc[a][b][d]=0.f;

    {
        load_a_tile(sb, g_ahi, g_alo, row0, 128, 0, t);   // c=0 is always a-planes col 0
        load_b_tile(sb, g_wgh, nb*4, t);
        CP_COMMIT();
    }
    for (int c=0;c<c1;c++){
        u32 st = sb + (u32)(c&1)*STAGE;
        if (c+1<c1){
            u32 nx = sb + (u32)((c+1)&1)*STAGE;
            const u16* SH = (c+1<2)? g_ahi : g_hhi;
            const u16* SL = (c+1<2)? g_alo : g_hlo;
            load_a_tile(nx, SH, SL, row0, 128, ((c+1)&1)*64, t);
            load_b_tile(nx, g_wgh, nb*4+c+1, t);
            CP_COMMIT();
            CP_WAIT1();
        } else CP_WAIT0();
        __syncthreads();
        compute_chunk(st, cacc, wm, wn, lane);
        __syncthreads();
    }
    store_g(cacc, row0, wm, wn, lane, nb);
}

// ---------------- GRU gates (float4; plane writes skipped on last step) ----------------
__global__ void __launch_bounds__(256) k_gru(const float* __restrict__ b_ih,
    const float* __restrict__ b_hh, float* __restrict__ hout, int last)
{
    int tid = blockIdx.x*256+threadIdx.x;
    if (tid >= NN*32) return;
    int row = tid>>5, p = (tid&31)*4;
    long gb = (long)row*512;
    float4 rv = *(const float4*)&g_g[gb + p];
    float4 zv = *(const float4*)&g_g[gb + 128 + p];
    float4 iv = *(const float4*)&g_g[gb + 256 + p];
    float4 nv = *(const float4*)&g_g[gb + 384 + p];
    float4 hv = *(const float4*)&g_h[(long)row*128 + p];
    const float* rp=(const float*)&rv; const float* zp=(const float*)&zv;
    const float* ip=(const float*)&iv; const float* np=(const float*)&nv;
    const float* hp=(const float*)&hv;
    float o[4]; u16 hh4[4], ll4[4];
#pragma unroll
    for (int j=0;j<4;j++){
        int f = p + j;
        float r_ = 1.f/(1.f + __expf(-(rp[j] + b_ih[f] + b_hh[f])));
        float z_ = 1.f/(1.f + __expf(-(zp[j] + b_ih[128+f] + b_hh[128+f])));
        float n_ = tanhf(ip[j] + b_ih[256+f] + r_*(np[j] + b_hh[256+f]));
        float out = (1.f - z_)*n_ + z_*hp[j];
        o[j] = out; hl(out, hh4[j], ll4[j]);
    }
    *(float4*)&hout[(long)row*128 + p] = *(float4*)o;
    if (!last){
        *(uint2*)&g_hhi[(long)row*128 + p] = *(uint2*)hh4;
        *(uint2*)&g_hlo[(long)row*128 + p] = *(uint2*)ll4;
    }
}

// ---------------- launch ----------------
extern "C" void kernel_launch(void* const* d_in, const int* in_sizes, int n_in,
                              void* d_out, int out_size)
{
    const float* h_in  = (const float*)d_in[0];
    const int*   src   = (const int*)d_in[1];
    const int*   dst   = (const int*)d_in[2];
    const int*   ety   = (const int*)d_in[3];
    const float* W_lin = (const float*)d_in[4];
    const float* b_lin = (const float*)d_in[5];
    const float* w_ih  = (const float*)d_in[6];
    const float* w_hh  = (const float*)d_in[7];
    const float* b_ih  = (const float*)d_in[8];
    const float* b_hh  = (const float*)d_in[9];

    cudaFuncSetAttribute(k_gemm_a, cudaFuncAttributeMaxDynamicSharedMemorySize, SMB);
    cudaFuncSetAttribute(k_gemm_g, cudaFuncAttributeMaxDynamicSharedMemorySize, SMB);

    float* h_p; cudaGetSymbolAddress((void**)&h_p, g_h);

    const int scan_blocks = (NSEG + 1023) / 1024;   // 196

    k_hist<<<(NE+255)/256,256>>>(dst, ety);
    k_scan1<<<scan_blocks,1024>>>();
    k_scan23<<<scan_blocks,1024>>>();
    k_place<<<(NE+255)/256,256>>>(src, dst, ety);
    k_setupinit<<<768,256>>>(W_lin, w_ih, w_hh, h_in);

    const int tilesA = (NN+127)/128;   // 391
    for (int step=0; step<NSTEP; step++){
        k_sbuild<<<(NSEG*32+255)/256,256>>>();
        k_gemm_a<<<dim3(tilesA,2),256,SMB>>>(b_lin);     // y=1 tail-fills with h_n block
        k_gemm_g<<<dim3(tilesA,3),256,SMB>>>();
        float* hout = (step==NSTEP-1) ? (float*)d_out : h_p;
        k_gru<<<(NN*32+255)/256,256>>>(b_ih, b_hh, hout, step==NSTEP-1);
    }
    (void)in_sizes; (void)n_in; (void)out_size;
}